// round 6
// baseline (speedup 1.0000x reference)
#include <cuda_runtime.h>
#include <math.h>
#include <stdint.h>

// Problem constants
#define Dm    1024
#define DQv   256
#define DHv   512
#define Pp    6
#define BATCH 8
#define Tt    2048
#define BT    (BATCH*Tt)       // 16384
#define NHEAD 8                // sign, aux, 6 digit heads
#define HBW   (NHEAD*DHv)      // 4096

// K-permutation within each 8-group: storage pos of original k
//   pos8(k) = 2*(k&3) + ((k>>2)&1)   => stored order [0,4,1,5,2,6,3,7]
__host__ __device__ __forceinline__ int permpos(int c) {
    return (c & ~7) | (2 * (c & 3) + ((c >> 2) & 1));
}

// ------------------- scratch (static device globals; no cudaMalloc) -------
__device__ float g_ctx[(size_t)BT * Dm];         // 64 MiB (pre-LN then tf32 ctx; K-permuted cols)
__device__ float g_hidr[(size_t)BT * Dm];        // 64 MiB (tf32 hidden, K-permuted cols)
__device__ float g_hbig[(size_t)BT * HBW];       // 256 MiB (pre-LN head hidden, natural order)
__device__ float g_opc[9 * Dm];
__device__ float g_ptc[10 * Dm];
__device__ float g_posc[Pp * DHv];
__device__ float g_gperm[Dm];                    // ctx_g permuted
__device__ float g_bperm[Dm];                    // ctx_beta permuted
__device__ float g_wctx_t[(size_t)Dm * Dm];      // ctx_w' [N,K] tf32, K-permuted
__device__ float g_whead_t[(size_t)NHEAD * DHv * Dm]; // W1' [512,1024] tf32, K-permuted

__device__ __forceinline__ float gelu_exact(float x) {
    return 0.5f * x * (1.0f + erff(x * 0.70710678118654752f));
}
__device__ __forceinline__ float to_tf32(float x) {
    asm("cvt.rna.tf32.f32 %0, %1;" : "=f"(x) : "f"(x));
    return x;
}
__device__ __forceinline__ uint32_t smem_u32(const void* p) {
    uint32_t a;
    asm("{ .reg .u64 t; cvta.to.shared.u64 t, %1; cvt.u32.u64 %0, t; }" : "=r"(a) : "l"(p));
    return a;
}
__device__ __forceinline__ void cp16(uint32_t dst, const void* src) {
    asm volatile("cp.async.cg.shared.global [%0], [%1], 16;" :: "r"(dst), "l"(src));
}
#define CP_COMMIT() asm volatile("cp.async.commit_group;" ::: "memory")
#define CP_WAIT1()  asm volatile("cp.async.wait_group 1;" ::: "memory")
#define CP_WAIT0()  asm volatile("cp.async.wait_group 0;" ::: "memory")

__device__ __forceinline__ void mma_tf32(float* c, const uint32_t* a, const uint32_t* b) {
    asm volatile("mma.sync.aligned.m16n8k8.row.col.f32.tf32.tf32.f32 "
        "{%0,%1,%2,%3}, {%4,%5,%6,%7}, {%8,%9}, {%0,%1,%2,%3};"
        : "+f"(c[0]), "+f"(c[1]), "+f"(c[2]), "+f"(c[3])
        : "r"(a[0]), "r"(a[1]), "r"(a[2]), "r"(a[3]), "r"(b[0]), "r"(b[1]));
}

// ------------------- precompute embedding contributions + permuted LN params
__global__ void precompute_kernel(const float* __restrict__ op_embed,
                                  const float* __restrict__ pt_embed,
                                  const float* __restrict__ pos_embed,
                                  const float* __restrict__ ctx_w,
                                  const float* __restrict__ dig_w1,
                                  const float* __restrict__ ctx_g,
                                  const float* __restrict__ ctx_beta) {
    int idx = blockIdx.x * blockDim.x + threadIdx.x;
    if (idx < 9 * Dm) {
        int i = idx >> 10, n = idx & (Dm - 1);
        float s = 0.f;
        #pragma unroll 4
        for (int q = 0; q < DQv; q++)
            s += op_embed[i * DQv + q] * ctx_w[(size_t)(Dm + q) * Dm + n];
        g_opc[idx] = s;
    } else if (idx < 19 * Dm) {
        int j = idx - 9 * Dm;
        int i = j >> 10, n = j & (Dm - 1);
        float s = 0.f;
        #pragma unroll 4
        for (int q = 0; q < DQv; q++)
            s += pt_embed[i * DQv + q] * ctx_w[(size_t)(Dm + DQv + q) * Dm + n];
        g_ptc[j] = s;
    } else if (idx < 19 * Dm + Pp * DHv) {
        int j = idx - 19 * Dm;
        int p = j >> 9, h = j & (DHv - 1);
        float s = 0.f;
        #pragma unroll 4
        for (int q = 0; q < DQv; q++)
            s += pos_embed[p * DQv + q] * dig_w1[(size_t)p * 1280 * DHv + (size_t)(Dm + q) * DHv + h];
        g_posc[j] = s;
    } else if (idx < 19 * Dm + Pp * DHv + Dm) {
        int k = idx - (19 * Dm + Pp * DHv);
        g_gperm[permpos(k)] = ctx_g[k];
        g_bperm[permpos(k)] = ctx_beta[k];
    }
}

// ------------------- round hidden to tf32 + K-permute ---------------------
// each thread handles 8 cols (one full permutation group)
__global__ __launch_bounds__(256) void round_hidden(const float* __restrict__ hidden) {
    size_t i8 = (size_t)(blockIdx.x * 256 + threadIdx.x) * 8;
    float4 lo = *(const float4*)(hidden + i8);
    float4 hi = *(const float4*)(hidden + i8 + 4);
    float2 o0 = make_float2(to_tf32(lo.x), to_tf32(hi.x));
    float2 o1 = make_float2(to_tf32(lo.y), to_tf32(hi.y));
    float2 o2 = make_float2(to_tf32(lo.z), to_tf32(hi.z));
    float2 o3 = make_float2(to_tf32(lo.w), to_tf32(hi.w));
    *(float2*)(g_hidr + i8 + 0) = o0;
    *(float2*)(g_hidr + i8 + 2) = o1;
    *(float2*)(g_hidr + i8 + 4) = o2;
    *(float2*)(g_hidr + i8 + 6) = o3;
}

// ------------------- weight transpose: [K=1024, N] -> [N, Kperm] tf32 -----
__global__ __launch_bounds__(256) void transpose_w(const float* __restrict__ ctx_w,
                                                   const float* __restrict__ sign_w1,
                                                   const float* __restrict__ aux_w1,
                                                   const float* __restrict__ dig_w1) {
    __shared__ float tbuf[32][33];
    int mat = blockIdx.z;
    const float* src; float* dst; int ncols;
    if (mat == 0)      { src = ctx_w;   dst = g_wctx_t;                     ncols = Dm; }
    else if (mat == 1) { src = sign_w1; dst = g_whead_t;                    ncols = DHv; }
    else if (mat == 2) { src = aux_w1;  dst = g_whead_t + (size_t)DHv * Dm; ncols = DHv; }
    else {
        int p = mat - 3;
        src = dig_w1 + (size_t)p * 1280 * DHv;
        dst = g_whead_t + (size_t)(2 + p) * DHv * Dm;
        ncols = DHv;
    }
    int n0 = blockIdx.x * 32;
    int k0 = blockIdx.y * 32;
    if (n0 >= ncols) return;
    #pragma unroll
    for (int j = 0; j < 4; j++)
        tbuf[threadIdx.y + j * 8][threadIdx.x] =
            src[(size_t)(k0 + threadIdx.y + j * 8) * ncols + n0 + threadIdx.x];
    __syncthreads();
    #pragma unroll
    for (int j = 0; j < 4; j++) {
        float v = tbuf[threadIdx.x][threadIdx.y + j * 8];
        dst[(size_t)(n0 + threadIdx.y + j * 8) * Dm + permpos(k0 + threadIdx.x)] = to_tf32(v);
    }
}

// ------------------- tf32 mma.sync GEMM (128x128 tile, K=1024, Kperm) -----
#define NKT 32
#define LDSP 36                       // padded cols (floats), even for float2
#define STAGEF (2 * 128 * LDSP)       // floats per stage (A+B)

__global__ __launch_bounds__(256, 2) void mma_gemm(int mode,
                                                   const int* __restrict__ op_t,
                                                   const int* __restrict__ pt_t,
                                                   const float* __restrict__ ctx_b,
                                                   const float* __restrict__ sign_b1,
                                                   const float* __restrict__ aux_b1,
                                                   const float* __restrict__ dig_b1) {
    extern __shared__ float smem[];
    uint32_t sbase = smem_u32(smem);

    int tid = threadIdx.x;
    int wid = tid >> 5, lane = tid & 31;
    int grp = lane >> 2, thr = lane & 3;
    int wm = (wid >> 2) * 64, wn = (wid & 3) * 32;
    int bn = blockIdx.x * 128, bm = blockIdx.y * 128, z = blockIdx.z;

    const float* Aptr = (mode == 0 ? g_hidr : g_ctx) + (size_t)bm * Dm;
    const float* Bptr = (mode == 0 ? g_wctx_t : g_whead_t + (size_t)z * DHv * Dm)
                        + (size_t)bn * Dm;

    float acc[4][4][4];
    #pragma unroll
    for (int a = 0; a < 4; a++)
        #pragma unroll
        for (int b = 0; b < 4; b++)
            #pragma unroll
            for (int c = 0; c < 4; c++) acc[a][b][c] = 0.f;

    // issue stage 0
    {
        uint32_t sA = sbase, sB = sbase + 128 * LDSP * 4;
        #pragma unroll
        for (int j = 0; j < 4; j++) {
            int idx = tid + j * 256;
            int r = idx >> 3, c = (idx & 7) << 2;
            cp16(sA + (uint32_t)(r * LDSP + c) * 4, Aptr + (size_t)r * Dm + c);
            cp16(sB + (uint32_t)(r * LDSP + c) * 4, Bptr + (size_t)r * Dm + c);
        }
        CP_COMMIT();
    }

    for (int kt = 0; kt < NKT; kt++) {
        int buf = kt & 1;
        if (kt + 1 < NKT) {
            int k0 = (kt + 1) * 32;
            uint32_t sA = sbase + (uint32_t)(buf ^ 1) * STAGEF * 4;
            uint32_t sB = sA + 128 * LDSP * 4;
            #pragma unroll
            for (int j = 0; j < 4; j++) {
                int idx = tid + j * 256;
                int r = idx >> 3, c = (idx & 7) << 2;
                cp16(sA + (uint32_t)(r * LDSP + c) * 4, Aptr + (size_t)r * Dm + k0 + c);
                cp16(sB + (uint32_t)(r * LDSP + c) * 4, Bptr + (size_t)r * Dm + k0 + c);
            }
            CP_COMMIT();
            CP_WAIT1();
        } else {
            CP_WAIT0();
        }
        __syncthreads();

        const float* Asb = smem + buf * STAGEF;
        const float* Bsb = Asb + 128 * LDSP;
        #pragma unroll
        for (int ks = 0; ks < 4; ks++) {
            int kk2 = ks * 8 + 2 * thr;   // permuted pos: (.x -> k=thr, .y -> k=thr+4)
            uint32_t af[4][4], bf[4][2];
            #pragma unroll
            for (int im = 0; im < 4; im++) {
                int rb = wm + im * 16 + grp;
                float2 lo = *(const float2*)&Asb[rb * LDSP + kk2];
                float2 hi = *(const float2*)&Asb[(rb + 8) * LDSP + kk2];
                af[im][0] = __float_as_uint(lo.x);
                af[im][1] = __float_as_uint(hi.x);
                af[im][2] = __float_as_uint(lo.y);
                af[im][3] = __float_as_uint(hi.y);
            }
            #pragma unroll
            for (int in = 0; in < 4; in++) {
                int nb = wn + in * 8 + grp;
                float2 bv = *(const float2*)&Bsb[nb * LDSP + kk2];
                bf[in][0] = __float_as_uint(bv.x);
                bf[in][1] = __float_as_uint(bv.y);
            }
            #pragma unroll
            for (int im = 0; im < 4; im++)
                #pragma unroll
                for (int in = 0; in < 4; in++)
                    mma_tf32(acc[im][in], af[im], bf[in]);
        }
        __syncthreads();
    }

    // ---- epilogue ----
    const float* b1 = nullptr; const float* posc = nullptr;
    if (mode == 1) {
        if (z == 0)      b1 = sign_b1;
        else if (z == 1) b1 = aux_b1;
        else { b1 = dig_b1 + (z - 2) * DHv; posc = g_posc + (z - 2) * DHv; }
    }
    #pragma unroll
    for (int im = 0; im < 4; im++) {
        #pragma unroll
        for (int half = 0; half < 2; half++) {
            int row = bm + wm + im * 16 + grp + half * 8;
            if (mode == 0) {
                int op = op_t[row >> 11];
                int pt = pt_t[row];
                const float* ocp = g_opc + op * Dm + bn;
                const float* pcp = g_ptc + pt * Dm + bn;
                const float* bpv = ctx_b + bn;
                float* dst = g_ctx + (size_t)row * Dm + bn;
                #pragma unroll
                for (int in = 0; in < 4; in++) {
                    int cl = wn + in * 8 + 2 * thr;
                    // write to K-permuted positions (g_ctx is mode-1's A)
                    dst[permpos(cl)]     = acc[im][in][half * 2 + 0] + ocp[cl]     + pcp[cl]     + bpv[cl];
                    dst[permpos(cl + 1)] = acc[im][in][half * 2 + 1] + ocp[cl + 1] + pcp[cl + 1] + bpv[cl + 1];
                }
            } else {
                float* dst = g_hbig + (size_t)row * HBW + z * DHv + bn;
                #pragma unroll
                for (int in = 0; in < 4; in++) {
                    int cl = wn + in * 8 + 2 * thr;
                    int col = bn + cl;
                    float2 v;
                    v.x = acc[im][in][half * 2 + 0] + b1[col];
                    v.y = acc[im][in][half * 2 + 1] + b1[col + 1];
                    if (posc) { v.x += posc[col]; v.y += posc[col + 1]; }
                    *(float2*)(dst + cl) = v;
                }
            }
        }
    }
}

// ------------------- LN(1024) + GELU over g_ctx (permuted space) ----------
__global__ __launch_bounds__(256) void ln_gelu_ctx() {
    int row = blockIdx.x;
    int tid = threadIdx.x;
    int lane = tid & 31, wid = tid >> 5;
    float* base = g_ctx + (size_t)row * Dm;
    float4 v = *(float4*)&base[tid * 4];
    float s  = v.x + v.y + v.z + v.w;
    float ss = v.x * v.x + v.y * v.y + v.z * v.z + v.w * v.w;
    #pragma unroll
    for (int off = 16; off; off >>= 1) {
        s  += __shfl_xor_sync(0xffffffffu, s, off);
        ss += __shfl_xor_sync(0xffffffffu, ss, off);
    }
    __shared__ float sh_s[8], sh_ss[8];
    if (lane == 0) { sh_s[wid] = s; sh_ss[wid] = ss; }
    __syncthreads();
    if (tid == 0) {
        float a = 0.f, b2 = 0.f;
        #pragma unroll
        for (int i = 0; i < 8; i++) { a += sh_s[i]; b2 += sh_ss[i]; }
        sh_s[0] = a; sh_ss[0] = b2;
    }
    __syncthreads();
    float mean = sh_s[0] * (1.f / Dm);
    float var  = sh_ss[0] * (1.f / Dm) - mean * mean;
    float rstd = rsqrtf(var + 1e-5f);
    int c = tid * 4;
    float4 gv = *(float4*)&g_gperm[c];
    float4 bv = *(float4*)&g_bperm[c];
    float4 o;
    o.x = to_tf32(gelu_exact((v.x - mean) * rstd * gv.x + bv.x));
    o.y = to_tf32(gelu_exact((v.y - mean) * rstd * gv.y + bv.y));
    o.z = to_tf32(gelu_exact((v.z - mean) * rstd * gv.z + bv.z));
    o.w = to_tf32(gelu_exact((v.w - mean) * rstd * gv.w + bv.w));
    *(float4*)&base[c] = o;
}

// ------------------- final: LN(512)+GELU + tiny GEMM (512 -> oc), fused ---
__global__ __launch_bounds__(256) void head_final(const float* __restrict__ sign_g,
                                                  const float* __restrict__ sign_beta,
                                                  const float* __restrict__ sign_w2,
                                                  const float* __restrict__ sign_b2,
                                                  const float* __restrict__ dig_g,
                                                  const float* __restrict__ dig_beta,
                                                  const float* __restrict__ dig_w2,
                                                  const float* __restrict__ dig_b2,
                                                  const float* __restrict__ aux_w2,
                                                  const float* __restrict__ aux_b2,
                                                  float* __restrict__ out) {
    int head = blockIdx.y;
    int oc; bool ln;
    const float *g = nullptr, *bt = nullptr, *w2, *b2;
    if (head == 0)      { oc = 3;  ln = true;  g = sign_g; bt = sign_beta; w2 = sign_w2; b2 = sign_b2; }
    else if (head == 1) { oc = 1;  ln = false; w2 = aux_w2; b2 = aux_b2; }
    else {
        int p = head - 2;
        oc = 10; ln = true;
        g = dig_g + p * DHv; bt = dig_beta + p * DHv;
        w2 = dig_w2 + (size_t)p * DHv * 10; b2 = dig_b2 + p * 10;
    }

    __shared__ float w2s[10 * DHv];
    for (int i = threadIdx.x; i < DHv * oc; i += 256) {
        int k = i / oc, o = i - k * oc;
        w2s[o * DHv + k] = w2[i];
    }
    __syncthreads();

    int wid = threadIdx.x >> 5, lane = threadIdx.x & 31;
    int row = blockIdx.x * 8 + wid;
    const float* hb = g_hbig + (size_t)row * HBW + head * DHv;

    float v[16];
    #pragma unroll
    for (int j = 0; j < 16; j++)
        v[j] = hb[lane + 32 * j];

    float mean = 0.f, rstd = 1.f;
    if (ln) {
        float s = 0.f, ss = 0.f;
        #pragma unroll
        for (int j = 0; j < 16; j++) { s += v[j]; ss += v[j] * v[j]; }
        #pragma unroll
        for (int off = 16; off; off >>= 1) {
            s  += __shfl_xor_sync(0xffffffffu, s, off);
            ss += __shfl_xor_sync(0xffffffffu, ss, off);
        }
        mean = s * (1.f / DHv);
        float var = ss * (1.f / DHv) - mean * mean;
        rstd = rsqrtf(var + 1e-5f);
    }

    float psum[10];
    #pragma unroll
    for (int o = 0; o < 10; o++) psum[o] = 0.f;

    #pragma unroll
    for (int j = 0; j < 16; j++) {
        int k = lane + 32 * j;
        float x = v[j];
        if (ln) x = (x - mean) * rstd * g[k] + bt[k];
        x = gelu_exact(x);
        #pragma unroll
        for (int o = 0; o < 10; o++)
            if (o < oc) psum[o] = fmaf(x, w2s[o * DHv + k], psum[o]);
    }
    #pragma unroll
    for (int o = 0; o < 10; o++)
        if (o < oc)
            #pragma unroll
            for (int off = 16; off; off >>= 1)
                psum[o] += __shfl_xor_sync(0xffffffffu, psum[o], off);

    if (lane == 0) {
        if (head == 0) {
            for (int o = 0; o < 3; o++) out[(size_t)row * 3 + o] = psum[o] + b2[o];
        } else if (head == 1) {
            out[(size_t)BT * 63 + row] = psum[0] + b2[0];
        } else {
            int p = head - 2;
            for (int o = 0; o < 10; o++)
                out[(size_t)BT * 3 + (size_t)row * 60 + p * 10 + o] = psum[o] + b2[o];
        }
    }
}

// ------------------- launch ------------------------------------------------
extern "C" void kernel_launch(void* const* d_in, const int* in_sizes, int n_in,
                              void* d_out, int out_size) {
    const float* hidden    = (const float*)d_in[0];
    const int*   op_t      = (const int*)  d_in[1];
    const int*   pt_t      = (const int*)  d_in[2];
    const float* op_embed  = (const float*)d_in[3];
    const float* pt_embed  = (const float*)d_in[4];
    const float* pos_embed = (const float*)d_in[5];
    const float* ctx_w     = (const float*)d_in[6];
    const float* ctx_b     = (const float*)d_in[7];
    const float* ctx_g     = (const float*)d_in[8];
    const float* ctx_beta  = (const float*)d_in[9];
    const float* sign_w1   = (const float*)d_in[10];
    const float* sign_b1   = (const float*)d_in[11];
    const float* sign_g    = (const float*)d_in[12];
    const float* sign_beta = (const float*)d_in[13];
    const float* sign_w2   = (const float*)d_in[14];
    const float* sign_b2   = (const float*)d_in[15];
    const float* dig_w1    = (const float*)d_in[16];
    const float* dig_b1    = (const float*)d_in[17];
    const float* dig_g     = (const float*)d_in[18];
    const float* dig_beta  = (const float*)d_in[19];
    const float* dig_w2    = (const float*)d_in[20];
    const float* dig_b2    = (const float*)d_in[21];
    const float* aux_w1    = (const float*)d_in[22];
    const float* aux_b1    = (const float*)d_in[23];
    const float* aux_w2    = (const float*)d_in[24];
    const float* aux_b2    = (const float*)d_in[25];
    float* out = (float*)d_out;

    const int SMEM_REQ = 2 * STAGEF * 4;   // 73728 B
    static int attr_set = 0;
    if (!attr_set) {
        cudaFuncSetAttribute(mma_gemm, cudaFuncAttributeMaxDynamicSharedMemorySize, SMEM_REQ);
        attr_set = 1;
    }

    // 1. embedding-contribution precompute + permuted LN params
    precompute_kernel<<<(19 * Dm + Pp * DHv + Dm + 255) / 256, 256>>>(
        op_embed, pt_embed, pos_embed, ctx_w, dig_w1, ctx_g, ctx_beta);

    // 2. weight transpose -> K-major tf32 (K-permuted) + round/permute hidden
    transpose_w<<<dim3(32, 32, 9), dim3(32, 8)>>>(ctx_w, sign_w1, aux_w1, dig_w1);
    round_hidden<<<(BT * Dm / 8) / 256, 256>>>(hidden);

    // 3. context GEMM (pre-LN): [16384,1024] x [1024,1024]  (tf32 mma.sync)
    mma_gemm<<<dim3(Dm / 128, BT / 128, 1), 256, SMEM_REQ>>>(
        0, op_t, pt_t, ctx_b, sign_b1, aux_b1, dig_b1);

    // 4. LN + GELU -> context (permuted space, tf32-rounded)
    ln_gelu_ctx<<<BT, 256>>>();

    // 5. all 8 head GEMMs: [16384,1024] x [1024,512] x8  (tf32 mma.sync)
    mma_gemm<<<dim3(DHv / 128, BT / 128, NHEAD), 256, SMEM_REQ>>>(
        1, op_t, pt_t, ctx_b, sign_b1, aux_b1, dig_b1);

    // 6. LN(512)+GELU + 512->oc projections, fused per-row warps
    head_final<<<dim3(BT / 8, NHEAD), 256>>>(
        sign_g, sign_beta, sign_w2, sign_b2,
        dig_g, dig_beta, dig_w2, dig_b2,
        aux_w2, aux_b2, out);
}

// round 7
// speedup vs baseline: 1.0902x; 1.0902x over previous
#include <cuda_runtime.h>
#include <math.h>
#include <stdint.h>

// Problem constants
#define Dm    1024
#define DQv   256
#define DHv   512
#define Pp    6
#define BATCH 8
#define Tt    2048
#define BT    (BATCH*Tt)       // 16384
#define NHEAD 8                // sign, aux, 6 digit heads
#define HBW   (NHEAD*DHv)      // 4096

// ------------------- scratch (static device globals; no cudaMalloc) -------
__device__ float g_ctx[(size_t)BT * Dm];         // 64 MiB  (pre-LN then tf32 context)
__device__ float g_hidr[(size_t)BT * Dm];        // 64 MiB  (tf32-rounded hidden)
__device__ float g_hbig[(size_t)BT * HBW];       // 256 MiB (pre-LN head hidden)
__device__ float g_opc[9 * Dm];
__device__ float g_ptc[10 * Dm];
__device__ float g_posc[Pp * DHv];
__device__ float g_wctx_t[(size_t)Dm * Dm];      // ctx_w[0:1024,:]^T  [N=1024,K=1024] tf32
__device__ float g_whead_t[(size_t)NHEAD * DHv * Dm]; // per-head W1[:1024,:]^T [512,1024] tf32

__device__ __forceinline__ float gelu_exact(float x) {
    return 0.5f * x * (1.0f + erff(x * 0.70710678118654752f));
}
__device__ __forceinline__ float to_tf32(float x) {
    asm("cvt.rna.tf32.f32 %0, %1;" : "=f"(x) : "f"(x));
    return x;
}
__device__ __forceinline__ uint32_t smem_u32(const void* p) {
    uint32_t a;
    asm("{ .reg .u64 t; cvta.to.shared.u64 t, %1; cvt.u32.u64 %0, t; }" : "=r"(a) : "l"(p));
    return a;
}
__device__ __forceinline__ void cp16(uint32_t dst, const void* src) {
    asm volatile("cp.async.cg.shared.global [%0], [%1], 16;" :: "r"(dst), "l"(src));
}
#define CP_COMMIT() asm volatile("cp.async.commit_group;" ::: "memory")
#define CP_WAIT1()  asm volatile("cp.async.wait_group 1;" ::: "memory")
#define CP_WAIT0()  asm volatile("cp.async.wait_group 0;" ::: "memory")

__device__ __forceinline__ void mma_tf32(float* c, const uint32_t* a, const uint32_t* b) {
    asm volatile("mma.sync.aligned.m16n8k8.row.col.f32.tf32.tf32.f32 "
        "{%0,%1,%2,%3}, {%4,%5,%6,%7}, {%8,%9}, {%0,%1,%2,%3};"
        : "+f"(c[0]), "+f"(c[1]), "+f"(c[2]), "+f"(c[3])
        : "r"(a[0]), "r"(a[1]), "r"(a[2]), "r"(a[3]), "r"(b[0]), "r"(b[1]));
}

// ------------------- precompute embedding contributions -------------------
__global__ void precompute_kernel(const float* __restrict__ op_embed,
                                  const float* __restrict__ pt_embed,
                                  const float* __restrict__ pos_embed,
                                  const float* __restrict__ ctx_w,
                                  const float* __restrict__ dig_w1) {
    int idx = blockIdx.x * blockDim.x + threadIdx.x;
    if (idx < 9 * Dm) {
        int i = idx >> 10, n = idx & (Dm - 1);
        float s = 0.f;
        #pragma unroll 4
        for (int q = 0; q < DQv; q++)
            s += op_embed[i * DQv + q] * ctx_w[(size_t)(Dm + q) * Dm + n];
        g_opc[idx] = s;
    } else if (idx < 19 * Dm) {
        int j = idx - 9 * Dm;
        int i = j >> 10, n = j & (Dm - 1);
        float s = 0.f;
        #pragma unroll 4
        for (int q = 0; q < DQv; q++)
            s += pt_embed[i * DQv + q] * ctx_w[(size_t)(Dm + DQv + q) * Dm + n];
        g_ptc[j] = s;
    } else if (idx < 19 * Dm + Pp * DHv) {
        int j = idx - 19 * Dm;
        int p = j >> 9, h = j & (DHv - 1);
        float s = 0.f;
        #pragma unroll 4
        for (int q = 0; q < DQv; q++)
            s += pos_embed[p * DQv + q] * dig_w1[(size_t)p * 1280 * DHv + (size_t)(Dm + q) * DHv + h];
        g_posc[j] = s;
    }
}

// ------------------- round hidden to tf32 (rna) ---------------------------
__global__ __launch_bounds__(256) void round_hidden(const float* __restrict__ hidden) {
    size_t i = (size_t)(blockIdx.x * 256 + threadIdx.x) * 4;
    float4 v = *(const float4*)(hidden + i);
    v.x = to_tf32(v.x); v.y = to_tf32(v.y);
    v.z = to_tf32(v.z); v.w = to_tf32(v.w);
    *(float4*)(g_hidr + i) = v;
}

// ------------------- weight transpose: [K=1024, N] -> [N, K] tf32 ---------
__global__ __launch_bounds__(256) void transpose_w(const float* __restrict__ ctx_w,
                                                   const float* __restrict__ sign_w1,
                                                   const float* __restrict__ aux_w1,
                                                   const float* __restrict__ dig_w1) {
    __shared__ float tbuf[32][33];
    int mat = blockIdx.z;
    const float* src; float* dst; int ncols;
    if (mat == 0)      { src = ctx_w;   dst = g_wctx_t;                     ncols = Dm; }
    else if (mat == 1) { src = sign_w1; dst = g_whead_t;                    ncols = DHv; }
    else if (mat == 2) { src = aux_w1;  dst = g_whead_t + (size_t)DHv * Dm; ncols = DHv; }
    else {
        int p = mat - 3;
        src = dig_w1 + (size_t)p * 1280 * DHv;
        dst = g_whead_t + (size_t)(2 + p) * DHv * Dm;
        ncols = DHv;
    }
    int n0 = blockIdx.x * 32;
    int k0 = blockIdx.y * 32;
    if (n0 >= ncols) return;
    #pragma unroll
    for (int j = 0; j < 4; j++)
        tbuf[threadIdx.y + j * 8][threadIdx.x] =
            src[(size_t)(k0 + threadIdx.y + j * 8) * ncols + n0 + threadIdx.x];
    __syncthreads();
    #pragma unroll
    for (int j = 0; j < 4; j++) {
        float v = tbuf[threadIdx.x][threadIdx.y + j * 8];
        dst[(size_t)(n0 + threadIdx.y + j * 8) * Dm + k0 + threadIdx.x] = to_tf32(v);
    }
}

// ------------------- tf32 mma.sync GEMM (128x256 block, 64x64/warp) -------
// mode 0: grid (4,128,1)   mode 1: grid (2,128,8)
#define NKT 32
#define LDSP 36                       // padded cols (floats)
#define ASZ  (128 * LDSP)             // A tile floats per stage
#define BSZ  (256 * LDSP)             // B tile floats per stage
#define STAGEF (ASZ + BSZ)

__global__ __launch_bounds__(256) void mma_gemm(int mode,
                                                const int* __restrict__ op_t,
                                                const int* __restrict__ pt_t,
                                                const float* __restrict__ ctx_b,
                                                const float* __restrict__ sign_b1,
                                                const float* __restrict__ aux_b1,
                                                const float* __restrict__ dig_b1) {
    extern __shared__ float smem[];
    uint32_t sbase = smem_u32(smem);

    int tid = threadIdx.x;
    int wid = tid >> 5, lane = tid & 31;
    int grp = lane >> 2, thr = lane & 3;
    int wm = (wid >> 2) * 64, wn = (wid & 3) * 64;
    int bn = blockIdx.x * 256, bm = blockIdx.y * 128, z = blockIdx.z;

    const float* Aptr = (mode == 0 ? g_hidr : g_ctx) + (size_t)bm * Dm;
    const float* Bptr = (mode == 0 ? g_wctx_t : g_whead_t + (size_t)z * DHv * Dm)
                        + (size_t)bn * Dm;

    float acc[4][8][4];
    #pragma unroll
    for (int a = 0; a < 4; a++)
        #pragma unroll
        for (int b = 0; b < 8; b++)
            #pragma unroll
            for (int c = 0; c < 4; c++) acc[a][b][c] = 0.f;

    // issue stage 0
    {
        uint32_t sA = sbase, sB = sbase + ASZ * 4;
        #pragma unroll
        for (int j = 0; j < 4; j++) {
            int idx = tid + j * 256;
            int r = idx >> 3, c = (idx & 7) << 2;
            cp16(sA + (uint32_t)(r * LDSP + c) * 4, Aptr + (size_t)r * Dm + c);
        }
        #pragma unroll
        for (int j = 0; j < 8; j++) {
            int idx = tid + j * 256;
            int r = idx >> 3, c = (idx & 7) << 2;
            cp16(sB + (uint32_t)(r * LDSP + c) * 4, Bptr + (size_t)r * Dm + c);
        }
        CP_COMMIT();
    }

    for (int kt = 0; kt < NKT; kt++) {
        int buf = kt & 1;
        if (kt + 1 < NKT) {
            int k0 = (kt + 1) * 32;
            uint32_t sA = sbase + (uint32_t)(buf ^ 1) * STAGEF * 4;
            uint32_t sB = sA + ASZ * 4;
            #pragma unroll
            for (int j = 0; j < 4; j++) {
                int idx = tid + j * 256;
                int r = idx >> 3, c = (idx & 7) << 2;
                cp16(sA + (uint32_t)(r * LDSP + c) * 4, Aptr + (size_t)r * Dm + k0 + c);
            }
            #pragma unroll
            for (int j = 0; j < 8; j++) {
                int idx = tid + j * 256;
                int r = idx >> 3, c = (idx & 7) << 2;
                cp16(sB + (uint32_t)(r * LDSP + c) * 4, Bptr + (size_t)r * Dm + k0 + c);
            }
            CP_COMMIT();
            CP_WAIT1();
        } else {
            CP_WAIT0();
        }
        __syncthreads();

        const float* Asb = smem + buf * STAGEF;
        const float* Bsb = Asb + ASZ;
        #pragma unroll
        for (int ks = 0; ks < 4; ks++) {
            int kk = ks * 8 + thr;
            uint32_t bf[8][2];
            #pragma unroll
            for (int in = 0; in < 8; in++) {
                int nb = wn + in * 8 + grp;
                bf[in][0] = __float_as_uint(Bsb[nb * LDSP + kk]);
                bf[in][1] = __float_as_uint(Bsb[nb * LDSP + kk + 4]);
            }
            #pragma unroll
            for (int im = 0; im < 4; im++) {
                int rb = wm + im * 16 + grp;
                uint32_t af[4];
                af[0] = __float_as_uint(Asb[rb * LDSP + kk]);
                af[1] = __float_as_uint(Asb[(rb + 8) * LDSP + kk]);
                af[2] = __float_as_uint(Asb[rb * LDSP + kk + 4]);
                af[3] = __float_as_uint(Asb[(rb + 8) * LDSP + kk + 4]);
                #pragma unroll
                for (int in = 0; in < 8; in++)
                    mma_tf32(acc[im][in], af, bf[in]);
            }
        }
        __syncthreads();
    }

    // ---- epilogue ----
    const float* b1 = nullptr; const float* posc = nullptr;
    if (mode == 1) {
        if (z == 0)      b1 = sign_b1;
        else if (z == 1) b1 = aux_b1;
        else { b1 = dig_b1 + (z - 2) * DHv; posc = g_posc + (z - 2) * DHv; }
    }
    #pragma unroll
    for (int im = 0; im < 4; im++) {
        #pragma unroll
        for (int half = 0; half < 2; half++) {
            int row = bm + wm + im * 16 + grp + half * 8;
            if (mode == 0) {
                int op = op_t[row >> 11];
                int pt = pt_t[row];
                const float* ocp = g_opc + op * Dm + bn;
                const float* pcp = g_ptc + pt * Dm + bn;
                const float* bpv = ctx_b + bn;
                float* dst = g_ctx + (size_t)row * Dm + bn;
                #pragma unroll
                for (int in = 0; in < 8; in++) {
                    int cl = wn + in * 8 + 2 * thr;
                    float2 v;
                    v.x = acc[im][in][half * 2 + 0] + ocp[cl]     + pcp[cl]     + bpv[cl];
                    v.y = acc[im][in][half * 2 + 1] + ocp[cl + 1] + pcp[cl + 1] + bpv[cl + 1];
                    *(float2*)(dst + cl) = v;
                }
            } else {
                float* dst = g_hbig + (size_t)row * HBW + z * DHv + bn;
                #pragma unroll
                for (int in = 0; in < 8; in++) {
                    int cl = wn + in * 8 + 2 * thr;
                    int col = bn + cl;
                    float2 v;
                    v.x = acc[im][in][half * 2 + 0] + b1[col];
                    v.y = acc[im][in][half * 2 + 1] + b1[col + 1];
                    if (posc) { v.x += posc[col]; v.y += posc[col + 1]; }
                    *(float2*)(dst + cl) = v;
                }
            }
        }
    }
}

// ------------------- LN(1024) + GELU over g_ctx, in place (tf32 out) ------
__global__ __launch_bounds__(256) void ln_gelu_ctx(const float* __restrict__ g,
                                                   const float* __restrict__ beta) {
    int row = blockIdx.x;
    int tid = threadIdx.x;
    int lane = tid & 31, wid = tid >> 5;
    float* base = g_ctx + (size_t)row * Dm;
    float4 v = *(float4*)&base[tid * 4];
    float s  = v.x + v.y + v.z + v.w;
    float ss = v.x * v.x + v.y * v.y + v.z * v.z + v.w * v.w;
    #pragma unroll
    for (int off = 16; off; off >>= 1) {
        s  += __shfl_xor_sync(0xffffffffu, s, off);
        ss += __shfl_xor_sync(0xffffffffu, ss, off);
    }
    __shared__ float sh_s[8], sh_ss[8];
    if (lane == 0) { sh_s[wid] = s; sh_ss[wid] = ss; }
    __syncthreads();
    if (tid == 0) {
        float a = 0.f, b2 = 0.f;
        #pragma unroll
        for (int i = 0; i < 8; i++) { a += sh_s[i]; b2 += sh_ss[i]; }
        sh_s[0] = a; sh_ss[0] = b2;
    }
    __syncthreads();
    float mean = sh_s[0] * (1.f / Dm);
    float var  = sh_ss[0] * (1.f / Dm) - mean * mean;
    float rstd = rsqrtf(var + 1e-5f);
    int c = tid * 4;
    float4 o;
    o.x = to_tf32(gelu_exact((v.x - mean) * rstd * g[c + 0] + beta[c + 0]));
    o.y = to_tf32(gelu_exact((v.y - mean) * rstd * g[c + 1] + beta[c + 1]));
    o.z = to_tf32(gelu_exact((v.z - mean) * rstd * g[c + 2] + beta[c + 2]));
    o.w = to_tf32(gelu_exact((v.w - mean) * rstd * g[c + 3] + beta[c + 3]));
    *(float4*)&base[c] = o;
}

// ------------------- final: LN(512)+GELU + tiny GEMM (512 -> oc), fused ---
__global__ __launch_bounds__(256) void head_final(const float* __restrict__ sign_g,
                                                  const float* __restrict__ sign_beta,
                                                  const float* __restrict__ sign_w2,
                                                  const float* __restrict__ sign_b2,
                                                  const float* __restrict__ dig_g,
                                                  const float* __restrict__ dig_beta,
                                                  const float* __restrict__ dig_w2,
                                                  const float* __restrict__ dig_b2,
                                                  const float* __restrict__ aux_w2,
                                                  const float* __restrict__ aux_b2,
                                                  float* __restrict__ out) {
    int head = blockIdx.y;
    int oc; bool ln;
    const float *g = nullptr, *bt = nullptr, *w2, *b2;
    if (head == 0)      { oc = 3;  ln = true;  g = sign_g; bt = sign_beta; w2 = sign_w2; b2 = sign_b2; }
    else if (head == 1) { oc = 1;  ln = false; w2 = aux_w2; b2 = aux_b2; }
    else {
        int p = head - 2;
        oc = 10; ln = true;
        g = dig_g + p * DHv; bt = dig_beta + p * DHv;
        w2 = dig_w2 + (size_t)p * DHv * 10; b2 = dig_b2 + p * 10;
    }

    __shared__ float w2s[10 * DHv];
    for (int i = threadIdx.x; i < DHv * oc; i += 256) {
        int k = i / oc, o = i - k * oc;
        w2s[o * DHv + k] = w2[i];
    }
    __syncthreads();

    int wid = threadIdx.x >> 5, lane = threadIdx.x & 31;
    int row = blockIdx.x * 8 + wid;
    const float* hb = g_hbig + (size_t)row * HBW + head * DHv;

    float v[16];
    #pragma unroll
    for (int j = 0; j < 16; j++)
        v[j] = hb[lane + 32 * j];

    float mean = 0.f, rstd = 1.f;
    if (ln) {
        float s = 0.f, ss = 0.f;
        #pragma unroll
        for (int j = 0; j < 16; j++) { s += v[j]; ss += v[j] * v[j]; }
        #pragma unroll
        for (int off = 16; off; off >>= 1) {
            s  += __shfl_xor_sync(0xffffffffu, s, off);
            ss += __shfl_xor_sync(0xffffffffu, ss, off);
        }
        mean = s * (1.f / DHv);
        float var = ss * (1.f / DHv) - mean * mean;
        rstd = rsqrtf(var + 1e-5f);
    }

    float psum[10];
    #pragma unroll
    for (int o = 0; o < 10; o++) psum[o] = 0.f;

    #pragma unroll
    for (int j = 0; j < 16; j++) {
        int k = lane + 32 * j;
        float x = v[j];
        if (ln) x = (x - mean) * rstd * g[k] + bt[k];
        x = gelu_exact(x);
        #pragma unroll
        for (int o = 0; o < 10; o++)
            if (o < oc) psum[o] = fmaf(x, w2s[o * DHv + k], psum[o]);
    }
    #pragma unroll
    for (int o = 0; o < 10; o++)
        if (o < oc)
            #pragma unroll
            for (int off = 16; off; off >>= 1)
                psum[o] += __shfl_xor_sync(0xffffffffu, psum[o], off);

    if (lane == 0) {
        if (head == 0) {
            for (int o = 0; o < 3; o++) out[(size_t)row * 3 + o] = psum[o] + b2[o];
        } else if (head == 1) {
            out[(size_t)BT * 63 + row] = psum[0] + b2[0];
        } else {
            int p = head - 2;
            for (int o = 0; o < 10; o++)
                out[(size_t)BT * 3 + (size_t)row * 60 + p * 10 + o] = psum[o] + b2[o];
        }
    }
}

// ------------------- launch ------------------------------------------------
extern "C" void kernel_launch(void* const* d_in, const int* in_sizes, int n_in,
                              void* d_out, int out_size) {
    const float* hidden    = (const float*)d_in[0];
    const int*   op_t      = (const int*)  d_in[1];
    const int*   pt_t      = (const int*)  d_in[2];
    const float* op_embed  = (const float*)d_in[3];
    const float* pt_embed  = (const float*)d_in[4];
    const float* pos_embed = (const float*)d_in[5];
    const float* ctx_w     = (const float*)d_in[6];
    const float* ctx_b     = (const float*)d_in[7];
    const float* ctx_g     = (const float*)d_in[8];
    const float* ctx_beta  = (const float*)d_in[9];
    const float* sign_w1   = (const float*)d_in[10];
    const float* sign_b1   = (const float*)d_in[11];
    const float* sign_g    = (const float*)d_in[12];
    const float* sign_beta = (const float*)d_in[13];
    const float* sign_w2   = (const float*)d_in[14];
    const float* sign_b2   = (const float*)d_in[15];
    const float* dig_w1    = (const float*)d_in[16];
    const float* dig_b1    = (const float*)d_in[17];
    const float* dig_g     = (const float*)d_in[18];
    const float* dig_beta  = (const float*)d_in[19];
    const float* dig_w2    = (const float*)d_in[20];
    const float* dig_b2    = (const float*)d_in[21];
    const float* aux_w1    = (const float*)d_in[22];
    const float* aux_b1    = (const float*)d_in[23];
    const float* aux_w2    = (const float*)d_in[24];
    const float* aux_b2    = (const float*)d_in[25];
    float* out = (float*)d_out;

    const int SMEM_REQ = 2 * STAGEF * 4;   // 110592 B
    static int attr_set = 0;
    if (!attr_set) {
        cudaFuncSetAttribute(mma_gemm, cudaFuncAttributeMaxDynamicSharedMemorySize, SMEM_REQ);
        attr_set = 1;
    }

    // 1. embedding-contribution precompute (tiny)
    precompute_kernel<<<(19 * Dm + Pp * DHv + 255) / 256, 256>>>(
        op_embed, pt_embed, pos_embed, ctx_w, dig_w1);

    // 2. weight transpose -> K-major tf32 + round hidden
    transpose_w<<<dim3(32, 32, 9), dim3(32, 8)>>>(ctx_w, sign_w1, aux_w1, dig_w1);
    round_hidden<<<(BT * Dm / 4) / 256, 256>>>(hidden);

    // 3. context GEMM (pre-LN): [16384,1024] x [1024,1024]  (tf32 mma.sync)
    mma_gemm<<<dim3(Dm / 256, BT / 128, 1), 256, SMEM_REQ>>>(
        0, op_t, pt_t, ctx_b, sign_b1, aux_b1, dig_b1);

    // 4. LN + GELU -> context (tf32-rounded)
    ln_gelu_ctx<<<BT, 256>>>(ctx_g, ctx_beta);

    // 5. all 8 head GEMMs: [16384,1024] x [1024,512] x8  (tf32 mma.sync)
    mma_gemm<<<dim3(DHv / 256, BT / 128, NHEAD), 256, SMEM_REQ>>>(
        1, op_t, pt_t, ctx_b, sign_b1, aux_b1, dig_b1);

    // 6. LN(512)+GELU + 512->oc projections, fused per-row warps
    head_final<<<dim3(BT / 8, NHEAD), 256>>>(
        sign_g, sign_beta, sign_w2, sign_b2,
        dig_g, dig_beta, dig_w2, dig_b2,
        aux_w2, aux_b2, out);
}

// round 8
// speedup vs baseline: 1.1879x; 1.0896x over previous
#include <cuda_runtime.h>
#include <math.h>
#include <stdint.h>

// Problem constants
#define Dm    1024
#define DQv   256
#define DHv   512
#define Pp    6
#define BATCH 8
#define Tt    2048
#define BT    (BATCH*Tt)       // 16384
#define NHEAD 8                // sign, aux, 6 digit heads
#define HBW   (NHEAD*DHv)      // 4096

// ------------------- scratch (static device globals; no cudaMalloc) -------
__device__ float g_ctx[(size_t)BT * Dm];         // 64 MiB  (pre-LN then tf32 context)
__device__ float g_hidr[(size_t)BT * Dm];        // 64 MiB  (tf32-rounded hidden)
__device__ float g_hbig[(size_t)BT * HBW];       // 256 MiB (pre-LN head hidden)
__device__ float g_opc[9 * Dm];
__device__ float g_ptc[10 * Dm];
__device__ float g_posc[Pp * DHv];
__device__ float g_wctx_t[(size_t)Dm * Dm];      // ctx_w[0:1024,:]^T  [N=1024,K=1024] tf32
__device__ float g_whead_t[(size_t)NHEAD * DHv * Dm]; // per-head W1[:1024,:]^T [512,1024] tf32

__device__ __forceinline__ float gelu_exact(float x) {
    return 0.5f * x * (1.0f + erff(x * 0.70710678118654752f));
}
__device__ __forceinline__ float to_tf32(float x) {
    asm("cvt.rna.tf32.f32 %0, %1;" : "=f"(x) : "f"(x));
    return x;
}
__device__ __forceinline__ uint32_t smem_u32(const void* p) {
    uint32_t a;
    asm("{ .reg .u64 t; cvta.to.shared.u64 t, %1; cvt.u32.u64 %0, t; }" : "=r"(a) : "l"(p));
    return a;
}
__device__ __forceinline__ void cp16(uint32_t dst, const void* src) {
    asm volatile("cp.async.cg.shared.global [%0], [%1], 16;" :: "r"(dst), "l"(src));
}
#define CP_COMMIT() asm volatile("cp.async.commit_group;" ::: "memory")
#define CP_WAIT1()  asm volatile("cp.async.wait_group 1;" ::: "memory")
#define CP_WAIT0()  asm volatile("cp.async.wait_group 0;" ::: "memory")

__device__ __forceinline__ void mma_tf32(float* c, const uint32_t* a, const uint32_t* b) {
    asm volatile("mma.sync.aligned.m16n8k8.row.col.f32.tf32.tf32.f32 "
        "{%0,%1,%2,%3}, {%4,%5,%6,%7}, {%8,%9}, {%0,%1,%2,%3};"
        : "+f"(c[0]), "+f"(c[1]), "+f"(c[2]), "+f"(c[3])
        : "r"(a[0]), "r"(a[1]), "r"(a[2]), "r"(a[3]), "r"(b[0]), "r"(b[1]));
}

// ------------------- precompute embedding contributions -------------------
__global__ void precompute_kernel(const float* __restrict__ op_embed,
                                  const float* __restrict__ pt_embed,
                                  const float* __restrict__ pos_embed,
                                  const float* __restrict__ ctx_w,
                                  const float* __restrict__ dig_w1) {
    int idx = blockIdx.x * blockDim.x + threadIdx.x;
    if (idx < 9 * Dm) {
        int i = idx >> 10, n = idx & (Dm - 1);
        float s = 0.f;
        #pragma unroll 4
        for (int q = 0; q < DQv; q++)
            s += op_embed[i * DQv + q] * ctx_w[(size_t)(Dm + q) * Dm + n];
        g_opc[idx] = s;
    } else if (idx < 19 * Dm) {
        int j = idx - 9 * Dm;
        int i = j >> 10, n = j & (Dm - 1);
        float s = 0.f;
        #pragma unroll 4
        for (int q = 0; q < DQv; q++)
            s += pt_embed[i * DQv + q] * ctx_w[(size_t)(Dm + DQv + q) * Dm + n];
        g_ptc[j] = s;
    } else if (idx < 19 * Dm + Pp * DHv) {
        int j = idx - 19 * Dm;
        int p = j >> 9, h = j & (DHv - 1);
        float s = 0.f;
        #pragma unroll 4
        for (int q = 0; q < DQv; q++)
            s += pos_embed[p * DQv + q] * dig_w1[(size_t)p * 1280 * DHv + (size_t)(Dm + q) * DHv + h];
        g_posc[j] = s;
    }
}

// ------------------- round hidden to tf32 (rna) ---------------------------
__global__ __launch_bounds__(256) void round_hidden(const float* __restrict__ hidden) {
    size_t i = (size_t)(blockIdx.x * 256 + threadIdx.x) * 4;
    float4 v = *(const float4*)(hidden + i);
    v.x = to_tf32(v.x); v.y = to_tf32(v.y);
    v.z = to_tf32(v.z); v.w = to_tf32(v.w);
    *(float4*)(g_hidr + i) = v;
}

// ------------------- weight transpose: [K=1024, N] -> [N, K] tf32 ---------
__global__ __launch_bounds__(256) void transpose_w(const float* __restrict__ ctx_w,
                                                   const float* __restrict__ sign_w1,
                                                   const float* __restrict__ aux_w1,
                                                   const float* __restrict__ dig_w1) {
    __shared__ float tbuf[32][33];
    int mat = blockIdx.z;
    const float* src; float* dst; int ncols;
    if (mat == 0)      { src = ctx_w;   dst = g_wctx_t;                     ncols = Dm; }
    else if (mat == 1) { src = sign_w1; dst = g_whead_t;                    ncols = DHv; }
    else if (mat == 2) { src = aux_w1;  dst = g_whead_t + (size_t)DHv * Dm; ncols = DHv; }
    else {
        int p = mat - 3;
        src = dig_w1 + (size_t)p * 1280 * DHv;
        dst = g_whead_t + (size_t)(2 + p) * DHv * Dm;
        ncols = DHv;
    }
    int n0 = blockIdx.x * 32;
    int k0 = blockIdx.y * 32;
    if (n0 >= ncols) return;
    #pragma unroll
    for (int j = 0; j < 4; j++)
        tbuf[threadIdx.y + j * 8][threadIdx.x] =
            src[(size_t)(k0 + threadIdx.y + j * 8) * ncols + n0 + threadIdx.x];
    __syncthreads();
    #pragma unroll
    for (int j = 0; j < 4; j++) {
        float v = tbuf[threadIdx.x][threadIdx.y + j * 8];
        dst[(size_t)(n0 + threadIdx.y + j * 8) * Dm + k0 + threadIdx.x] = to_tf32(v);
    }
}

// ------------------- tf32 mma.sync GEMM (128x128 block, 4 warps, 64x64/warp)
// mode 0: grid (8,128,1)   mode 1: grid (4,128,8)
#define NKT 32
#define LDSP 36                       // padded cols (floats)
#define ASZ  (128 * LDSP)             // A tile floats per stage
#define BSZ  (128 * LDSP)             // B tile floats per stage
#define STAGEF (ASZ + BSZ)

__global__ __launch_bounds__(128, 3) void mma_gemm(int mode,
                                                   const int* __restrict__ op_t,
                                                   const int* __restrict__ pt_t,
                                                   const float* __restrict__ ctx_b,
                                                   const float* __restrict__ sign_b1,
                                                   const float* __restrict__ aux_b1,
                                                   const float* __restrict__ dig_b1) {
    extern __shared__ float smem[];
    uint32_t sbase = smem_u32(smem);

    int tid = threadIdx.x;
    int wid = tid >> 5, lane = tid & 31;
    int grp = lane >> 2, thr = lane & 3;
    int wm = (wid >> 1) * 64, wn = (wid & 1) * 64;
    int bn = blockIdx.x * 128, bm = blockIdx.y * 128, z = blockIdx.z;

    const float* Aptr = (mode == 0 ? g_hidr : g_ctx) + (size_t)bm * Dm;
    const float* Bptr = (mode == 0 ? g_wctx_t : g_whead_t + (size_t)z * DHv * Dm)
                        + (size_t)bn * Dm;

    float acc[4][8][4];
    #pragma unroll
    for (int a = 0; a < 4; a++)
        #pragma unroll
        for (int b = 0; b < 8; b++)
            #pragma unroll
            for (int c = 0; c < 4; c++) acc[a][b][c] = 0.f;

    // issue stage 0 (128 threads: 8 cp16 each for A, 8 for B)
    {
        uint32_t sA = sbase, sB = sbase + ASZ * 4;
        #pragma unroll
        for (int j = 0; j < 8; j++) {
            int idx = tid + j * 128;
            int r = idx >> 3, c = (idx & 7) << 2;
            cp16(sA + (uint32_t)(r * LDSP + c) * 4, Aptr + (size_t)r * Dm + c);
            cp16(sB + (uint32_t)(r * LDSP + c) * 4, Bptr + (size_t)r * Dm + c);
        }
        CP_COMMIT();
    }

    for (int kt = 0; kt < NKT; kt++) {
        int buf = kt & 1;
        if (kt + 1 < NKT) {
            int k0 = (kt + 1) * 32;
            uint32_t sA = sbase + (uint32_t)(buf ^ 1) * STAGEF * 4;
            uint32_t sB = sA + ASZ * 4;
            #pragma unroll
            for (int j = 0; j < 8; j++) {
                int idx = tid + j * 128;
                int r = idx >> 3, c = (idx & 7) << 2;
                cp16(sA + (uint32_t)(r * LDSP + c) * 4, Aptr + (size_t)r * Dm + k0 + c);
                cp16(sB + (uint32_t)(r * LDSP + c) * 4, Bptr + (size_t)r * Dm + k0 + c);
            }
            CP_COMMIT();
            CP_WAIT1();
        } else {
            CP_WAIT0();
        }
        __syncthreads();

        const float* Asb = smem + buf * STAGEF;
        const float* Bsb = Asb + ASZ;
        #pragma unroll
        for (int ks = 0; ks < 4; ks++) {
            int kk = ks * 8 + thr;
            uint32_t bf[8][2];
            #pragma unroll
            for (int in = 0; in < 8; in++) {
                int nb = wn + in * 8 + grp;
                bf[in][0] = __float_as_uint(Bsb[nb * LDSP + kk]);
                bf[in][1] = __float_as_uint(Bsb[nb * LDSP + kk + 4]);
            }
            #pragma unroll
            for (int im = 0; im < 4; im++) {
                int rb = wm + im * 16 + grp;
                uint32_t af[4];
                af[0] = __float_as_uint(Asb[rb * LDSP + kk]);
                af[1] = __float_as_uint(Asb[(rb + 8) * LDSP + kk]);
                af[2] = __float_as_uint(Asb[rb * LDSP + kk + 4]);
                af[3] = __float_as_uint(Asb[(rb + 8) * LDSP + kk + 4]);
                #pragma unroll
                for (int in = 0; in < 8; in++)
                    mma_tf32(acc[im][in], af, bf[in]);
            }
        }
        __syncthreads();
    }

    // ---- epilogue ----
    const float* b1 = nullptr; const float* posc = nullptr;
    if (mode == 1) {
        if (z == 0)      b1 = sign_b1;
        else if (z == 1) b1 = aux_b1;
        else { b1 = dig_b1 + (z - 2) * DHv; posc = g_posc + (z - 2) * DHv; }
    }
    #pragma unroll
    for (int im = 0; im < 4; im++) {
        #pragma unroll
        for (int half = 0; half < 2; half++) {
            int row = bm + wm + im * 16 + grp + half * 8;
            if (mode == 0) {
                int op = op_t[row >> 11];
                int pt = pt_t[row];
                const float* ocp = g_opc + op * Dm + bn;
                const float* pcp = g_ptc + pt * Dm + bn;
                const float* bpv = ctx_b + bn;
                float* dst = g_ctx + (size_t)row * Dm + bn;
                #pragma unroll
                for (int in = 0; in < 8; in++) {
                    int cl = wn + in * 8 + 2 * thr;
                    float2 v;
                    v.x = acc[im][in][half * 2 + 0] + ocp[cl]     + pcp[cl]     + bpv[cl];
                    v.y = acc[im][in][half * 2 + 1] + ocp[cl + 1] + pcp[cl + 1] + bpv[cl + 1];
                    *(float2*)(dst + cl) = v;
                }
            } else {
                float* dst = g_hbig + (size_t)row * HBW + z * DHv + bn;
                #pragma unroll
                for (int in = 0; in < 8; in++) {
                    int cl = wn + in * 8 + 2 * thr;
                    int col = bn + cl;
                    float2 v;
                    v.x = acc[im][in][half * 2 + 0] + b1[col];
                    v.y = acc[im][in][half * 2 + 1] + b1[col + 1];
                    if (posc) { v.x += posc[col]; v.y += posc[col + 1]; }
                    *(float2*)(dst + cl) = v;
                }
            }
        }
    }
}

// ------------------- LN(1024) + GELU over g_ctx, in place (tf32 out) ------
__global__ __launch_bounds__(256) void ln_gelu_ctx(const float* __restrict__ g,
                                                   const float* __restrict__ beta) {
    int row = blockIdx.x;
    int tid = threadIdx.x;
    int lane = tid & 31, wid = tid >> 5;
    float* base = g_ctx + (size_t)row * Dm;
    float4 v = *(float4*)&base[tid * 4];
    float s  = v.x + v.y + v.z + v.w;
    float ss = v.x * v.x + v.y * v.y + v.z * v.z + v.w * v.w;
    #pragma unroll
    for (int off = 16; off; off >>= 1) {
        s  += __shfl_xor_sync(0xffffffffu, s, off);
        ss += __shfl_xor_sync(0xffffffffu, ss, off);
    }
    __shared__ float sh_s[8], sh_ss[8];
    if (lane == 0) { sh_s[wid] = s; sh_ss[wid] = ss; }
    __syncthreads();
    if (tid == 0) {
        float a = 0.f, b2 = 0.f;
        #pragma unroll
        for (int i = 0; i < 8; i++) { a += sh_s[i]; b2 += sh_ss[i]; }
        sh_s[0] = a; sh_ss[0] = b2;
    }
    __syncthreads();
    float mean = sh_s[0] * (1.f / Dm);
    float var  = sh_ss[0] * (1.f / Dm) - mean * mean;
    float rstd = rsqrtf(var + 1e-5f);
    int c = tid * 4;
    float4 o;
    o.x = to_tf32(gelu_exact((v.x - mean) * rstd * g[c + 0] + beta[c + 0]));
    o.y = to_tf32(gelu_exact((v.y - mean) * rstd * g[c + 1] + beta[c + 1]));
    o.z = to_tf32(gelu_exact((v.z - mean) * rstd * g[c + 2] + beta[c + 2]));
    o.w = to_tf32(gelu_exact((v.w - mean) * rstd * g[c + 3] + beta[c + 3]));
    *(float4*)&base[c] = o;
}

// ------------------- final: LN(512)+GELU + tiny GEMM (512 -> oc), fused ---
__global__ __launch_bounds__(256) void head_final(const float* __restrict__ sign_g,
                                                  const float* __restrict__ sign_beta,
                                                  const float* __restrict__ sign_w2,
                                                  const float* __restrict__ sign_b2,
                                                  const float* __restrict__ dig_g,
                                                  const float* __restrict__ dig_beta,
                                                  const float* __restrict__ dig_w2,
                                                  const float* __restrict__ dig_b2,
                                                  const float* __restrict__ aux_w2,
                                                  const float* __restrict__ aux_b2,
                                                  float* __restrict__ out) {
    int head = blockIdx.y;
    int oc; bool ln;
    const float *g = nullptr, *bt = nullptr, *w2, *b2;
    if (head == 0)      { oc = 3;  ln = true;  g = sign_g; bt = sign_beta; w2 = sign_w2; b2 = sign_b2; }
    else if (head == 1) { oc = 1;  ln = false; w2 = aux_w2; b2 = aux_b2; }
    else {
        int p = head - 2;
        oc = 10; ln = true;
        g = dig_g + p * DHv; bt = dig_beta + p * DHv;
        w2 = dig_w2 + (size_t)p * DHv * 10; b2 = dig_b2 + p * 10;
    }

    __shared__ float w2s[10 * DHv];
    for (int i = threadIdx.x; i < DHv * oc; i += 256) {
        int k = i / oc, o = i - k * oc;
        w2s[o * DHv + k] = w2[i];
    }
    __syncthreads();

    int wid = threadIdx.x >> 5, lane = threadIdx.x & 31;
    int row = blockIdx.x * 8 + wid;
    const float* hb = g_hbig + (size_t)row * HBW + head * DHv;

    float v[16];
    #pragma unroll
    for (int j = 0; j < 16; j++)
        v[j] = hb[lane + 32 * j];

    float mean = 0.f, rstd = 1.f;
    if (ln) {
        float s = 0.f, ss = 0.f;
        #pragma unroll
        for (int j = 0; j < 16; j++) { s += v[j]; ss += v[j] * v[j]; }
        #pragma unroll
        for (int off = 16; off; off >>= 1) {
            s  += __shfl_xor_sync(0xffffffffu, s, off);
            ss += __shfl_xor_sync(0xffffffffu, ss, off);
        }
        mean = s * (1.f / DHv);
        float var = ss * (1.f / DHv) - mean * mean;
        rstd = rsqrtf(var + 1e-5f);
    }

    float psum[10];
    #pragma unroll
    for (int o = 0; o < 10; o++) psum[o] = 0.f;

    #pragma unroll
    for (int j = 0; j < 16; j++) {
        int k = lane + 32 * j;
        float x = v[j];
        if (ln) x = (x - mean) * rstd * g[k] + bt[k];
        x = gelu_exact(x);
        #pragma unroll
        for (int o = 0; o < 10; o++)
            if (o < oc) psum[o] = fmaf(x, w2s[o * DHv + k], psum[o]);
    }
    #pragma unroll
    for (int o = 0; o < 10; o++)
        if (o < oc)
            #pragma unroll
            for (int off = 16; off; off >>= 1)
                psum[o] += __shfl_xor_sync(0xffffffffu, psum[o], off);

    if (lane == 0) {
        if (head == 0) {
            for (int o = 0; o < 3; o++) out[(size_t)row * 3 + o] = psum[o] + b2[o];
        } else if (head == 1) {
            out[(size_t)BT * 63 + row] = psum[0] + b2[0];
        } else {
            int p = head - 2;
            for (int o = 0; o < 10; o++)
                out[(size_t)BT * 3 + (size_t)row * 60 + p * 10 + o] = psum[o] + b2[o];
        }
    }
}

// ------------------- launch ------------------------------------------------
extern "C" void kernel_launch(void* const* d_in, const int* in_sizes, int n_in,
                              void* d_out, int out_size) {
    const float* hidden    = (const float*)d_in[0];
    const int*   op_t      = (const int*)  d_in[1];
    const int*   pt_t      = (const int*)  d_in[2];
    const float* op_embed  = (const float*)d_in[3];
    const float* pt_embed  = (const float*)d_in[4];
    const float* pos_embed = (const float*)d_in[5];
    const float* ctx_w     = (const float*)d_in[6];
    const float* ctx_b     = (const float*)d_in[7];
    const float* ctx_g     = (const float*)d_in[8];
    const float* ctx_beta  = (const float*)d_in[9];
    const float* sign_w1   = (const float*)d_in[10];
    const float* sign_b1   = (const float*)d_in[11];
    const float* sign_g    = (const float*)d_in[12];
    const float* sign_beta = (const float*)d_in[13];
    const float* sign_w2   = (const float*)d_in[14];
    const float* sign_b2   = (const float*)d_in[15];
    const float* dig_w1    = (const float*)d_in[16];
    const float* dig_b1    = (const float*)d_in[17];
    const float* dig_g     = (const float*)d_in[18];
    const float* dig_beta  = (const float*)d_in[19];
    const float* dig_w2    = (const float*)d_in[20];
    const float* dig_b2    = (const float*)d_in[21];
    const float* aux_w1    = (const float*)d_in[22];
    const float* aux_b1    = (const float*)d_in[23];
    const float* aux_w2    = (const float*)d_in[24];
    const float* aux_b2    = (const float*)d_in[25];
    float* out = (float*)d_out;

    const int SMEM_REQ = 2 * STAGEF * 4;   // 73728 B
    static int attr_set = 0;
    if (!attr_set) {
        cudaFuncSetAttribute(mma_gemm, cudaFuncAttributeMaxDynamicSharedMemorySize, SMEM_REQ);
        attr_set = 1;
    }

    // 1. embedding-contribution precompute (tiny)
    precompute_kernel<<<(19 * Dm + Pp * DHv + 255) / 256, 256>>>(
        op_embed, pt_embed, pos_embed, ctx_w, dig_w1);

    // 2. weight transpose -> K-major tf32 + round hidden
    transpose_w<<<dim3(32, 32, 9), dim3(32, 8)>>>(ctx_w, sign_w1, aux_w1, dig_w1);
    round_hidden<<<(BT * Dm / 4) / 256, 256>>>(hidden);

    // 3. context GEMM (pre-LN): [16384,1024] x [1024,1024]  (tf32 mma.sync)
    mma_gemm<<<dim3(Dm / 128, BT / 128, 1), 128, SMEM_REQ>>>(
        0, op_t, pt_t, ctx_b, sign_b1, aux_b1, dig_b1);

    // 4. LN + GELU -> context (tf32-rounded)
    ln_gelu_ctx<<<BT, 256>>>(ctx_g, ctx_beta);

    // 5. all 8 head GEMMs: [16384,1024] x [1024,512] x8  (tf32 mma.sync)
    mma_gemm<<<dim3(DHv / 128, BT / 128, NHEAD), 128, SMEM_REQ>>>(
        1, op_t, pt_t, ctx_b, sign_b1, aux_b1, dig_b1);

    // 6. LN(512)+GELU + 512->oc projections, fused per-row warps
    head_final<<<dim3(BT / 8, NHEAD), 256>>>(
        sign_g, sign_beta, sign_w2, sign_b2,
        dig_g, dig_beta, dig_w2, dig_b2,
        aux_w2, aux_b2, out);
}